// round 1
// baseline (speedup 1.0000x reference)
#include <cuda_runtime.h>
#include <math.h>

#define BATCH 16
#define CHAN  256
#define NPIX  4096

// Scratch (allocation-free: __device__ globals)
__device__ float g_energy[3u * BATCH * CHAN * CHAN];   // 12.6 MB
__device__ float g_attn[(unsigned)BATCH * CHAN * CHAN]; // 4.2 MB
__device__ float g_M[(unsigned)BATCH * CHAN * CHAN];    // 4.2 MB

// ---------------------------------------------------------------------------
// Kernel 1: energy[s][b][c][d] = sum_n x[b,c,n] * src_s[b,d,n]   (NT GEMM)
// Tile: TM=128 (c) x TN=64 (d) x TK=16, 256 threads, 8x4 micro-tile.
// Both operands are K-contiguous; tiles stored transposed in smem (padded)
// so the inner loop is pure vectorized LDS + FFMA.
// ---------------------------------------------------------------------------
__global__ __launch_bounds__(256, 2)
void energy_kernel(const float* __restrict__ x, const float* __restrict__ y,
                   const float* __restrict__ z)
{
    constexpr int TM = 128, TN = 64, TK = 16;
    constexpr int PA = 132, PB = 68;  // pads: 16B-aligned rows, low STS conflicts
    __shared__ float As[TK * PA];
    __shared__ float Bs[TK * PB];

    int id = blockIdx.x;
    int t  = id & 7;          // 8 tiles per (s,b): 2 cTiles x 4 dTiles
    int bs = id >> 3;
    int b  = bs & 15;
    int s  = bs >> 4;
    int cBase = (t >> 2) * TM;
    int dBase = (t & 3) * TN;

    const float* A = x + (size_t)b * (CHAN * NPIX);
    const float* S = (s == 0 ? x : (s == 1 ? y : z)) + (size_t)b * (CHAN * NPIX);

    int tid = threadIdx.x;
    int ty = tid >> 4, tx = tid & 15;
    int m0 = ty * 8, n0 = tx * 4;

    int mld = tid >> 2;        // 0..63
    int kc  = (tid & 3) * 4;   // 0,4,8,12

    const float* pA0 = A + (size_t)(cBase + mld) * NPIX + kc;
    const float* pA1 = pA0 + (size_t)64 * NPIX;
    const float* pB  = S + (size_t)(dBase + mld) * NPIX + kc;

    float4 ra0 = *(const float4*)pA0;
    float4 ra1 = *(const float4*)pA1;
    float4 rb  = *(const float4*)pB;

    float acc[8][4];
    #pragma unroll
    for (int i = 0; i < 8; i++)
        #pragma unroll
        for (int j = 0; j < 4; j++) acc[i][j] = 0.f;

    for (int kb = 0; kb < NPIX; kb += TK) {
        // transpose-store prefetched chunk
        As[(kc+0)*PA + mld] = ra0.x;
        As[(kc+1)*PA + mld] = ra0.y;
        As[(kc+2)*PA + mld] = ra0.z;
        As[(kc+3)*PA + mld] = ra0.w;
        As[(kc+0)*PA + 64 + mld] = ra1.x;
        As[(kc+1)*PA + 64 + mld] = ra1.y;
        As[(kc+2)*PA + 64 + mld] = ra1.z;
        As[(kc+3)*PA + 64 + mld] = ra1.w;
        Bs[(kc+0)*PB + mld] = rb.x;
        Bs[(kc+1)*PB + mld] = rb.y;
        Bs[(kc+2)*PB + mld] = rb.z;
        Bs[(kc+3)*PB + mld] = rb.w;
        __syncthreads();

        if (kb + TK < NPIX) {   // prefetch next chunk (LDG latency hidden)
            pA0 += TK; pA1 += TK; pB += TK;
            ra0 = *(const float4*)pA0;
            ra1 = *(const float4*)pA1;
            rb  = *(const float4*)pB;
        }

        #pragma unroll
        for (int k = 0; k < TK; k++) {
            float4 a0 = *(const float4*)&As[k*PA + m0];
            float4 a1 = *(const float4*)&As[k*PA + m0 + 4];
            float4 bq = *(const float4*)&Bs[k*PB + n0];
            float a[8] = {a0.x, a0.y, a0.z, a0.w, a1.x, a1.y, a1.z, a1.w};
            float bb[4] = {bq.x, bq.y, bq.z, bq.w};
            #pragma unroll
            for (int i = 0; i < 8; i++)
                #pragma unroll
                for (int j = 0; j < 4; j++)
                    acc[i][j] = fmaf(a[i], bb[j], acc[i][j]);
        }
        __syncthreads();
    }

    float* E = g_energy + ((size_t)s * BATCH + b) * (CHAN * CHAN);
    #pragma unroll
    for (int i = 0; i < 8; i++) {
        int c = cBase + m0 + i;
        float4 v = make_float4(acc[i][0], acc[i][1], acc[i][2], acc[i][3]);
        *(float4*)&E[(size_t)c * CHAN + dBase + n0] = v;
    }
}

// ---------------------------------------------------------------------------
// Kernel 2: attn[b][c][:] = sum_s softmax(rowmax(E_s[b][c]) - E_s[b][c])
// One block per (b,c) row; 256 threads = 256 columns.
// ---------------------------------------------------------------------------
__global__ void softmax_sum_kernel()
{
    int b = blockIdx.x >> 8;
    int c = blockIdx.x & 255;
    int t = threadIdx.x;
    __shared__ float red[256];

    float acc = 0.f;
    #pragma unroll
    for (int s = 0; s < 3; s++) {
        float e = g_energy[(((size_t)s * BATCH + b) * CHAN + c) * CHAN + t];
        // m1 = max(E)
        red[t] = e; __syncthreads();
        for (int o = 128; o > 0; o >>= 1) {
            if (t < o) red[t] = fmaxf(red[t], red[t + o]);
            __syncthreads();
        }
        float m1 = red[0]; __syncthreads();
        // v = m1 - E  (matches reference rounding path), m2 = max(v)
        float v = m1 - e;
        red[t] = v; __syncthreads();
        for (int o = 128; o > 0; o >>= 1) {
            if (t < o) red[t] = fmaxf(red[t], red[t + o]);
            __syncthreads();
        }
        float m2 = red[0]; __syncthreads();
        float p = expf(v - m2);
        red[t] = p; __syncthreads();
        for (int o = 128; o > 0; o >>= 1) {
            if (t < o) red[t] += red[t + o];
            __syncthreads();
        }
        float S = red[0]; __syncthreads();
        acc += p / S;
    }
    g_attn[((size_t)b * CHAN + c) * CHAN + t] = acc;
}

// ---------------------------------------------------------------------------
// Kernels 3/4: TN GEMM, C[m][n] = sum_k A[m][k]*B[k][n], K=256.
// A is K-contiguous (transposed into smem); B is n-contiguous (natural layout).
// Tile TM=64 x TN=128 x TK=16, 256 threads, 4x8 micro-tile (cols split
// {tx*4, 64+tx*4} for conflict-free LDS.128).
//   FINAL=false: O = gamma * acc                      (M = gamma * conv_w @ attn)
//   FINAL=true : O = acc + gamma*bias[m] + resid[idx] (out = M @ x + g*b + x)
// ---------------------------------------------------------------------------
template<int NCOLS, bool FINAL>
__global__ __launch_bounds__(256, 2)
void gemm_tn(const float* __restrict__ Ab, long aStride,
             const float* __restrict__ Bb, long bStride,
             float* __restrict__ Ob,
             const float* __restrict__ bias,
             const float* __restrict__ gamma_p,
             const float* __restrict__ resid)
{
    constexpr int TM = 64, TN = 128, TK = 16, Kdim = 256, PA = 68;
    constexpr int NT = NCOLS / TN;
    __shared__ float As[TK * PA];
    __shared__ float Bs[TK * TN];

    int id = blockIdx.x;
    int nt = id % NT; id /= NT;
    int mt = id & 3;
    int b  = id >> 2;
    int mBase = mt * TM, nBase = nt * TN;

    const float* A = Ab + (size_t)b * aStride;
    const float* B = Bb + (size_t)b * bStride;
    float* O = Ob + (size_t)b * ((size_t)CHAN * NCOLS);
    const float* R = FINAL ? (resid + (size_t)b * ((size_t)CHAN * NCOLS)) : nullptr;

    int tid = threadIdx.x;
    int ty = tid >> 4, tx = tid & 15;
    int m0 = ty * 4, n0 = tx * 4;

    int mldA = tid >> 2, kcA = (tid & 3) * 4;       // A: 256 float4, 1/thread
    int krB = tid >> 5, nvB = tid & 31;             // B: 512 float4, 2/thread

    const float* pA  = A + (size_t)(mBase + mldA) * Kdim + kcA;
    const float* pB0 = B + (size_t)krB * NCOLS + nBase + nvB * 4;
    const float* pB1 = pB0 + (size_t)8 * NCOLS;

    float4 ra  = *(const float4*)pA;
    float4 rb0 = *(const float4*)pB0;
    float4 rb1 = *(const float4*)pB1;

    float acc[4][8];
    #pragma unroll
    for (int i = 0; i < 4; i++)
        #pragma unroll
        for (int j = 0; j < 8; j++) acc[i][j] = 0.f;

    for (int kb = 0; kb < Kdim; kb += TK) {
        As[(kcA+0)*PA + mldA] = ra.x;
        As[(kcA+1)*PA + mldA] = ra.y;
        As[(kcA+2)*PA + mldA] = ra.z;
        As[(kcA+3)*PA + mldA] = ra.w;
        *(float4*)&Bs[krB * TN + nvB * 4]       = rb0;
        *(float4*)&Bs[(krB + 8) * TN + nvB * 4] = rb1;
        __syncthreads();

        if (kb + TK < Kdim) {
            pA += TK; pB0 += (size_t)TK * NCOLS; pB1 += (size_t)TK * NCOLS;
            ra  = *(const float4*)pA;
            rb0 = *(const float4*)pB0;
            rb1 = *(const float4*)pB1;
        }

        #pragma unroll
        for (int k = 0; k < TK; k++) {
            float4 a4 = *(const float4*)&As[k*PA + m0];
            float4 b0 = *(const float4*)&Bs[k*TN + n0];
            float4 b1 = *(const float4*)&Bs[k*TN + 64 + n0];
            float a[4]  = {a4.x, a4.y, a4.z, a4.w};
            float bb[8] = {b0.x, b0.y, b0.z, b0.w, b1.x, b1.y, b1.z, b1.w};
            #pragma unroll
            for (int i = 0; i < 4; i++)
                #pragma unroll
                for (int j = 0; j < 8; j++)
                    acc[i][j] = fmaf(a[i], bb[j], acc[i][j]);
        }
        __syncthreads();
    }

    float gamma = gamma_p[0];
    #pragma unroll
    for (int i = 0; i < 4; i++) {
        int row = mBase + m0 + i;
        size_t base = (size_t)row * NCOLS + nBase + n0;
        if (FINAL) {
            float gb = gamma * bias[row];
            float4 r0 = *(const float4*)&R[base];
            float4 r1 = *(const float4*)&R[base + 64];
            float4 o0 = make_float4(acc[i][0] + gb + r0.x, acc[i][1] + gb + r0.y,
                                    acc[i][2] + gb + r0.z, acc[i][3] + gb + r0.w);
            float4 o1 = make_float4(acc[i][4] + gb + r1.x, acc[i][5] + gb + r1.y,
                                    acc[i][6] + gb + r1.z, acc[i][7] + gb + r1.w);
            *(float4*)&O[base]      = o0;
            *(float4*)&O[base + 64] = o1;
        } else {
            float4 o0 = make_float4(gamma*acc[i][0], gamma*acc[i][1],
                                    gamma*acc[i][2], gamma*acc[i][3]);
            float4 o1 = make_float4(gamma*acc[i][4], gamma*acc[i][5],
                                    gamma*acc[i][6], gamma*acc[i][7]);
            *(float4*)&O[base]      = o0;
            *(float4*)&O[base + 64] = o1;
        }
    }
}

// ---------------------------------------------------------------------------
extern "C" void kernel_launch(void* const* d_in, const int* in_sizes, int n_in,
                              void* d_out, int out_size)
{
    const float* x      = (const float*)d_in[0];
    const float* y      = (const float*)d_in[1];
    const float* z      = (const float*)d_in[2];
    const float* conv_w = (const float*)d_in[3];
    const float* conv_b = (const float*)d_in[4];
    const float* gamma  = (const float*)d_in[5];
    float* out = (float*)d_out;

    float *pAttn, *pM;
    cudaGetSymbolAddress((void**)&pAttn, g_attn);
    cudaGetSymbolAddress((void**)&pM, g_M);

    // 1) three energy GEMMs: 3*16*8 = 384 CTAs
    energy_kernel<<<3 * BATCH * 8, 256>>>(x, y, z);
    // 2) softmax + sum over sources
    softmax_sum_kernel<<<BATCH * CHAN, 256>>>();
    // 3) M_b = gamma * conv_w @ attn_b   (256x256x256 per batch)
    gemm_tn<CHAN, false><<<BATCH * 4 * 2, 256>>>(
        conv_w, 0, pAttn, (long)CHAN * CHAN, pM, nullptr, gamma, nullptr);
    // 4) out = M_b @ x_b + gamma*conv_b + x   (256x4096x256 per batch)
    gemm_tn<NPIX, true><<<BATCH * 4 * 32, 256>>>(
        pM, (long)CHAN * CHAN, x, (long)CHAN * NPIX, out, conv_b, gamma, x);
}